// round 6
// baseline (speedup 1.0000x reference)
#include <cuda_runtime.h>
#include <cuda_bf16.h>
#include <cstdint>

#define BATCH   4096
#define NB      64
#define IN_DIM  256
#define NTOT    4096
#define DT_C    0.05f
#define TAU_EPS 1e-6f

// bf16 tile row pitch: 72 elems = 144 bytes (conflict-free ldmatrix)
#define PITCH   144
// fp32 y staging pitch (floats)
#define YPITCH  68

// ---------------- SMEM layout (byte offsets) ----------------
#define A0_OFF  0                       // 128x64 bf16 (y_prev | u chunk); later YB fp32
#define A1_OFF  18432                   // 128x64 bf16 (y_cur)
#define W0_OFF  36864                   // W_fwd[j-1] | W_in chunk
#define W1_OFF  46080                   // W_rec[j]
#define W2_OFF  55296                   // E_l[j]
#define W3_OFF  64512                   // E_l_r[j]
#define BR_OFF  73728
#define BF_OFF  (BR_OFF + 256)
#define IT_OFF  (BF_OFF + 256)
#define SMEM_TOTAL (IT_OFF + 256)       // 74496 B -> 3 CTAs/SM
#define YB_OFF  A0_OFF                  // fp32 y overlay (34816 B <= 36864)

// ---------------------------------------------------------------------------
__device__ __forceinline__ uint32_t smem_u32(const void* p) {
    uint32_t a;
    asm("{ .reg .u64 t; cvta.to.shared.u64 t, %1; cvt.u32.u64 %0, t; }"
        : "=r"(a) : "l"(p));
    return a;
}
__device__ __forceinline__ float tanh_fast(float x) {
    float r; asm("tanh.approx.f32 %0, %1;" : "=f"(r) : "f"(x)); return r;
}
__device__ __forceinline__ uint32_t bf2(float lo, float hi) {
    uint32_t r;
    asm("cvt.rn.bf16x2.f32 %0, %1, %2;" : "=r"(r) : "f"(hi), "f"(lo));
    return r;
}
__device__ __forceinline__ float2 ubf2(uint32_t v) {
    __nv_bfloat162 b = *reinterpret_cast<__nv_bfloat162*>(&v);
    return __bfloat1622float2(b);
}

#define LDM4(r, addr) \
    asm volatile("ldmatrix.sync.aligned.m8n8.x4.shared.b16 {%0,%1,%2,%3}, [%4];" \
        : "=r"((r)[0]), "=r"((r)[1]), "=r"((r)[2]), "=r"((r)[3]) : "r"(addr))

__device__ __forceinline__ void mma16816(float* c, const uint32_t* a,
                                         uint32_t b0, uint32_t b1) {
    asm volatile(
        "mma.sync.aligned.m16n8k16.row.col.f32.bf16.bf16.f32 "
        "{%0,%1,%2,%3}, {%4,%5,%6,%7}, {%8,%9}, {%0,%1,%2,%3};"
        : "+f"(c[0]), "+f"(c[1]), "+f"(c[2]), "+f"(c[3])
        : "r"(a[0]), "r"(a[1]), "r"(a[2]), "r"(a[3]), "r"(b0), "r"(b1));
}

// Warp computes C[32 x 64] += A_smem[32 x 64] * W_smem[64 x 64]^T
__device__ __forceinline__ void gemm32x64(uint32_t abase, uint32_t wbase,
                                          float acc[16][4], int lane, int warpM)
{
    uint32_t pa = abase + (uint32_t)((warpM + (lane & 7) + ((lane >> 3) & 1) * 8) * PITCH
                                     + ((lane >> 4) * 8) * 2);
    uint32_t pb = wbase + (uint32_t)((((lane & 7) + ((lane >> 4) & 1) * 8)) * PITCH
                                     + (((lane >> 3) & 1) * 8) * 2);
#pragma unroll
    for (int ks = 0; ks < 4; ks++) {
        uint32_t a0[4], a1[4];
        LDM4(a0, pa + ks * 32);
        LDM4(a1, pa + 16 * PITCH + ks * 32);
#pragma unroll
        for (int np = 0; np < 4; np++) {
            uint32_t b[4];
            LDM4(b, pb + np * 16 * PITCH + ks * 32);
            mma16816(acc[np * 2 + 0],     a0, b[0], b[1]);
            mma16816(acc[np * 2 + 1],     a0, b[2], b[3]);
            mma16816(acc[8 + np * 2 + 0], a1, b[0], b[1]);
            mma16816(acc[8 + np * 2 + 1], a1, b[2], b[3]);
        }
    }
}

// Warp computes C[32 x 64] += A_regs * W_smem^T ; A = packed bf16x2 fragments
__device__ __forceinline__ void gemm32x64_reg(uint32_t wbase,
                                              const uint32_t lo[2][8],
                                              const uint32_t hi[2][8],
                                              float acc[16][4], int lane)
{
    uint32_t pb = wbase + (uint32_t)((((lane & 7) + ((lane >> 4) & 1) * 8)) * PITCH
                                     + (((lane >> 3) & 1) * 8) * 2);
#pragma unroll
    for (int ks = 0; ks < 4; ks++) {
#pragma unroll
        for (int np = 0; np < 4; np++) {
            uint32_t b[4];
            LDM4(b, pb + np * 16 * PITCH + ks * 32);
#pragma unroll
            for (int mt = 0; mt < 2; mt++) {
                uint32_t a[4] = { lo[mt][2 * ks], hi[mt][2 * ks],
                                  lo[mt][2 * ks + 1], hi[mt][2 * ks + 1] };
                mma16816(acc[mt * 8 + np * 2 + 0], a, b[0], b[1]);
                mma16816(acc[mt * 8 + np * 2 + 1], a, b[2], b[3]);
            }
        }
    }
}

__device__ __forceinline__ void pack_tanh(const float acc[16][4], const float* bias,
                                          uint32_t lo[2][8], uint32_t hi[2][8],
                                          int lane)
{
    const int nb = (lane & 3) * 2;
#pragma unroll
    for (int mt = 0; mt < 2; mt++)
#pragma unroll
        for (int nt = 0; nt < 8; nt++) {
            const float* c = acc[mt * 8 + nt];
            float b0 = bias[nt * 8 + nb], b1 = bias[nt * 8 + nb + 1];
            lo[mt][nt] = bf2(tanh_fast(c[0] + b0), tanh_fast(c[1] + b1));
            hi[mt][nt] = bf2(tanh_fast(c[2] + b0), tanh_fast(c[3] + b1));
        }
}

__device__ __forceinline__ void zero_acc(float acc[16][4]) {
#pragma unroll
    for (int i = 0; i < 16; i++)
#pragma unroll
        for (int q = 0; q < 4; q++) acc[i][q] = 0.f;
}

__device__ __forceinline__ void stage128(char* dst, const float* __restrict__ src,
                                         int srcPitch, int t)
{
#pragma unroll
    for (int i = 0; i < 16; i++) {
        int idx = t + i * 128;
        int r = idx >> 4, c4 = idx & 15;
        float4 v = *(const float4*)&src[r * srcPitch + c4 * 4];
        *(uint2*)(dst + r * PITCH + c4 * 8) = make_uint2(bf2(v.x, v.y), bf2(v.z, v.w));
    }
}
__device__ __forceinline__ void stage64(char* dst, const float* __restrict__ src,
                                        int srcPitch, int t)
{
#pragma unroll
    for (int i = 0; i < 8; i++) {
        int idx = t + i * 128;
        int o = idx >> 4, c4 = idx & 15;
        float4 v = *(const float4*)&src[o * srcPitch + c4 * 4];
        *(uint2*)(dst + o * PITCH + c4 * 8) = make_uint2(bf2(v.x, v.y), bf2(v.z, v.w));
    }
}

// ---------------------------------------------------------------------------
// Single fused kernel. grid (32 batch tiles, 64 blocks j), 128 threads.
// ---------------------------------------------------------------------------
__global__ void __launch_bounds__(128, 3) ltc_main(
    const float* __restrict__ y,
    const float* __restrict__ u,
    const float* __restrict__ tau_raw,
    const float* __restrict__ Wi,  const float* __restrict__ bi,
    const float* __restrict__ Wf,  const float* __restrict__ bfw,
    const float* __restrict__ Wr,  const float* __restrict__ brw,
    const float* __restrict__ El,  const float* __restrict__ Elr,
    float* __restrict__ out)
{
    extern __shared__ char sm[];
    const int t     = threadIdx.x;
    const int lane  = t & 31;
    const int warpM = (t >> 5) * 32;
    const int bt    = blockIdx.x;
    const int j     = blockIdx.y;
    const int row0  = bt * 128;

    float* s_br = (float*)(sm + BR_OFF);
    float* s_bf = (float*)(sm + BF_OFF);
    float* s_it = (float*)(sm + IT_OFF);
    float* yb   = (float*)(sm + YB_OFF);
    const uint32_t smb = smem_u32(sm);

    // ---------------- Stage bf16 tiles ----------------
    stage128(sm + A1_OFF, y + (size_t)row0 * NTOT + j * 64, NTOT, t);
    if (j > 0) {
        stage128(sm + A0_OFF, y + (size_t)row0 * NTOT + (j - 1) * 64, NTOT, t);
        stage64(sm + W0_OFF, Wf + (j - 1) * 4096, 64, t);
    }
    stage64(sm + W1_OFF, Wr  + j * 4096, 64, t);
    stage64(sm + W2_OFF, El  + j * 4096, 64, t);
    stage64(sm + W3_OFF, Elr + j * 4096, 64, t);
    if (t < 64) {
        s_br[t] = brw[j * 64 + t];
        s_bf[t] = (j > 0) ? bfw[(j - 1) * 64 + t] : bi[t];
        float x  = tau_raw[j * 64 + t];
        float sp = (x > 20.f) ? x : log1pf(expf(x));
        s_it[t]  = 1.0f / (sp + TAU_EPS);
    }
    __syncthreads();

    float acc[16][4];
    uint32_t nr_lo[2][8], nr_hi[2][8];
    uint32_t no_lo[2][8], no_hi[2][8];

    // ---------------- Phase 1a: net_rec = tanh(y_cur @ Wr^T + br) ----------
    zero_acc(acc);
    gemm32x64(smb + A1_OFF, smb + W1_OFF, acc, lane, warpM);
    pack_tanh(acc, s_br, nr_lo, nr_hi, lane);

    // ---------------- Phase 1b: net_out ------------------------------------
    zero_acc(acc);
    if (j > 0) {
        gemm32x64(smb + A0_OFF, smb + W0_OFF, acc, lane, warpM);
    } else {
        for (int kc = 0; kc < 4; kc++) {
            __syncthreads();
            stage128(sm + A0_OFF, u + (size_t)row0 * IN_DIM + kc * 64, IN_DIM, t);
            stage64(sm + W0_OFF, Wi + kc * 64, IN_DIM, t);
            __syncthreads();
            gemm32x64(smb + A0_OFF, smb + W0_OFF, acc, lane, warpM);
        }
    }
    pack_tanh(acc, s_bf, no_lo, no_hi, lane);

    // A0/A1 bf16 tiles are now dead (phase 2 reads A from registers).
    __syncthreads();

    // ---------------- Restage exact fp32 y into YB (coalesced, L2-hot) ----
    // Issued before phase-2 MMAs so the load latency hides behind tensor work.
#pragma unroll
    for (int i = 0; i < 16; i++) {
        int idx = t + i * 128;
        int r = idx >> 4, c4 = idx & 15;
        float4 v = *(const float4*)&y[(size_t)(row0 + r) * NTOT + j * 64 + c4 * 4];
        *(float4*)&yb[r * YPITCH + c4 * 4] = v;
    }

    // ---------------- Phase 2: drive = net_out@El^T + net_rec@Elr^T --------
    zero_acc(acc);
    gemm32x64_reg(smb + W2_OFF, no_lo, no_hi, acc, lane);
    gemm32x64_reg(smb + W3_OFF, nr_lo, nr_hi, acc, lane);

    __syncthreads();   // YB fully staged by all threads; phase-2 done

    // ---------------- Epilogue: fragment-wise combine, in-place in YB ------
    {
        const int gm = warpM + (lane >> 2);
        const int nb = (lane & 3) * 2;
#pragma unroll
        for (int mt = 0; mt < 2; mt++)
#pragma unroll
            for (int nt = 0; nt < 8; nt++) {
                int n = nt * 8 + nb;
                float it0 = s_it[n], it1 = s_it[n + 1];
                float2 no0 = ubf2(no_lo[mt][nt]), no1 = ubf2(no_hi[mt][nt]);
                float2 nr0 = ubf2(nr_lo[mt][nt]), nr1 = ubf2(nr_hi[mt][nt]);
                const float* c = acc[mt * 8 + nt];
                int m0 = gm + mt * 16;
                float2 ya = *(const float2*)&yb[m0 * YPITCH + n];
                float2 yc = *(const float2*)&yb[(m0 + 8) * YPITCH + n];
                float2 o0, o1;
                o0.x = (ya.x + DT_C * c[0]) /
                       (1.f + DT_C * (it0 + fabsf(no0.x) + fabsf(nr0.x)));
                o0.y = (ya.y + DT_C * c[1]) /
                       (1.f + DT_C * (it1 + fabsf(no0.y) + fabsf(nr0.y)));
                o1.x = (yc.x + DT_C * c[2]) /
                       (1.f + DT_C * (it0 + fabsf(no1.x) + fabsf(nr1.x)));
                o1.y = (yc.y + DT_C * c[3]) /
                       (1.f + DT_C * (it1 + fabsf(no1.y) + fabsf(nr1.y)));
                *(float2*)&yb[m0 * YPITCH + n] = o0;
                *(float2*)&yb[(m0 + 8) * YPITCH + n] = o1;
            }
    }
    __syncthreads();

    // ---------------- Coalesced store ----------------
#pragma unroll
    for (int i = 0; i < 16; i++) {
        int idx = t + i * 128;
        int r = idx >> 4, c4 = idx & 15;
        float4 v = *(const float4*)&yb[r * YPITCH + c4 * 4];
        *(float4*)&out[(size_t)(row0 + r) * NTOT + j * 64 + c4 * 4] = v;
    }
}

// ---------------------------------------------------------------------------
extern "C" void kernel_launch(void* const* d_in, const int* in_sizes, int n_in,
                              void* d_out, int out_size) {
    const float* y   = (const float*)d_in[0];
    const float* u_t = (const float*)d_in[1];
    const float* tau = (const float*)d_in[2];
    const float* Wi  = (const float*)d_in[3];
    const float* bi  = (const float*)d_in[4];
    const float* Wf  = (const float*)d_in[5];
    const float* bfw = (const float*)d_in[6];
    const float* Wr  = (const float*)d_in[7];
    const float* brw = (const float*)d_in[8];
    const float* El  = (const float*)d_in[9];
    const float* Elr = (const float*)d_in[10];
    float* out = (float*)d_out;

    cudaFuncSetAttribute(ltc_main, cudaFuncAttributeMaxDynamicSharedMemorySize,
                         SMEM_TOTAL);

    ltc_main<<<dim3(BATCH / 128, NB), 128, SMEM_TOTAL>>>(
        y, u_t, tau, Wi, bi, Wf, bfw, Wr, brw, El, Elr, out);
}

// round 7
// speedup vs baseline: 1.3599x; 1.3599x over previous
#include <cuda_runtime.h>
#include <cuda_bf16.h>
#include <cstdint>

#define BATCH   4096
#define NB      64
#define IN_DIM  256
#define NTOT    4096
#define DT_C    0.05f
#define TAU_EPS 1e-6f

// bf16 tile row pitch: 72 elems = 144 bytes (odd 16B-groups -> conflict-free ldmatrix)
#define PITCH   144

// ---------------- ltc_main SMEM layout (byte offsets) ----------------
#define A0_OFF  0                       // 128 x 64 bf16 (y_prev/net0 -> net_out)
#define A1_OFF  18432                   // 128 x 64 bf16 (y_cur -> net_rec)
#define W0_OFF  36864                   // W_fwd[j-1] 64x64 bf16
#define W1_OFF  46080                   // W_rec[j]
#define W2_OFF  55296                   // E_l[j]
#define W3_OFF  64512                   // E_l_r[j]
#define YB_OFF  73728                   // 128 x 66 fp32 exact y -> y_new
#define BR_OFF  (YB_OFF + 128*66*4)     // 107520
#define BF_OFF  (BR_OFF + 256)
#define IT_OFF  (BF_OFF + 256)
#define SMEM_TOTAL (IT_OFF + 256)       // 108288 bytes -> 2 CTAs/SM

// ---------------- net0 SMEM layout ----------------
#define N0_PITCH 528                    // 256 bf16 = 512B + 16B pad (odd 16B groups)
#define N0_U_OFF 0                      // 64 x 528
#define N0_W_OFF 33792                  // 64 x 528
#define N0_B_OFF 67584                  // 64 f32
#define N0_SMEM  (N0_B_OFF + 256)

__device__ float g_net0[BATCH * 64];

// ---------------------------------------------------------------------------
// helpers
// ---------------------------------------------------------------------------
__device__ __forceinline__ uint32_t smem_u32(const void* p) {
    uint32_t a;
    asm("{ .reg .u64 t; cvta.to.shared.u64 t, %1; cvt.u32.u64 %0, t; }"
        : "=r"(a) : "l"(p));
    return a;
}
__device__ __forceinline__ float tanh_fast(float x) {
    float r; asm("tanh.approx.f32 %0, %1;" : "=f"(r) : "f"(x)); return r;
}
__device__ __forceinline__ uint32_t bf2(float lo, float hi) {
    uint32_t r;
    asm("cvt.rn.bf16x2.f32 %0, %1, %2;" : "=r"(r) : "f"(hi), "f"(lo));
    return r;
}
__device__ __forceinline__ float2 ubf2(uint32_t v) {
    __nv_bfloat162 b = *reinterpret_cast<__nv_bfloat162*>(&v);
    return __bfloat1622float2(b);
}

#define LDM4(r, addr) \
    asm volatile("ldmatrix.sync.aligned.m8n8.x4.shared.b16 {%0,%1,%2,%3}, [%4];" \
        : "=r"((r)[0]), "=r"((r)[1]), "=r"((r)[2]), "=r"((r)[3]) : "r"(addr))

__device__ __forceinline__ void mma16816(float* c, const uint32_t* a,
                                         uint32_t b0, uint32_t b1) {
    asm volatile(
        "mma.sync.aligned.m16n8k16.row.col.f32.bf16.bf16.f32 "
        "{%0,%1,%2,%3}, {%4,%5,%6,%7}, {%8,%9}, {%0,%1,%2,%3};"
        : "+f"(c[0]), "+f"(c[1]), "+f"(c[2]), "+f"(c[3])
        : "r"(a[0]), "r"(a[1]), "r"(a[2]), "r"(a[3]), "r"(b0), "r"(b1));
}

// Warp computes C[32 x 64] += A_smem[32 x 64] * W_smem[64 x 64]^T
__device__ __forceinline__ void gemm32x64(uint32_t abase, uint32_t wbase,
                                          float acc[16][4], int lane, int warpM)
{
    uint32_t pa = abase + (uint32_t)((warpM + (lane & 7) + ((lane >> 3) & 1) * 8) * PITCH
                                     + ((lane >> 4) * 8) * 2);
    uint32_t pb = wbase + (uint32_t)((((lane & 7) + ((lane >> 4) & 1) * 8)) * PITCH
                                     + (((lane >> 3) & 1) * 8) * 2);
#pragma unroll
    for (int ks = 0; ks < 4; ks++) {
        uint32_t a0[4], a1[4];
        LDM4(a0, pa + ks * 32);
        LDM4(a1, pa + 16 * PITCH + ks * 32);
#pragma unroll
        for (int np = 0; np < 4; np++) {
            uint32_t b[4];
            LDM4(b, pb + np * 16 * PITCH + ks * 32);
            mma16816(acc[np * 2 + 0],     a0, b[0], b[1]);
            mma16816(acc[np * 2 + 1],     a0, b[2], b[3]);
            mma16816(acc[8 + np * 2 + 0], a1, b[0], b[1]);
            mma16816(acc[8 + np * 2 + 1], a1, b[2], b[3]);
        }
    }
}

__device__ __forceinline__ void tanh_store(const float acc[16][4], const float* bias,
                                           char* dst, int lane, int warpM)
{
    const int gm = warpM + (lane >> 2);
    const int nb = (lane & 3) * 2;
#pragma unroll
    for (int mt = 0; mt < 2; mt++)
#pragma unroll
        for (int nt = 0; nt < 8; nt++) {
            const float* c = acc[mt * 8 + nt];
            int n  = nt * 8 + nb;
            float b0 = bias[n], b1 = bias[n + 1];
            int m0 = gm + mt * 16;
            *(uint32_t*)(dst + m0 * PITCH + n * 2) =
                bf2(tanh_fast(c[0] + b0), tanh_fast(c[1] + b1));
            *(uint32_t*)(dst + (m0 + 8) * PITCH + n * 2) =
                bf2(tanh_fast(c[2] + b0), tanh_fast(c[3] + b1));
        }
}

// ---------------------------------------------------------------------------
// Kernel 1: net0 = tanh(u_t @ W_in^T + b_in)  via bf16 mma.
// grid = 64 (batch tiles of 64), block = 128 (4 warps, m16 each), K = 256.
// ---------------------------------------------------------------------------
__global__ void __launch_bounds__(128) net0_kernel(const float* __restrict__ u,
                                                   const float* __restrict__ Wi,
                                                   const float* __restrict__ bi) {
    extern __shared__ char sm[];
    const int t    = threadIdx.x;
    const int lane = t & 31;
    const int w    = t >> 5;
    const int bt   = blockIdx.x;
    const uint32_t smb = smem_u32(sm);
    float* s_bi = (float*)(sm + N0_B_OFF);

    // stage u tile [64 x 256] and Wi [64 x 256] as bf16
#pragma unroll
    for (int i = 0; i < 32; i++) {
        int idx = t + i * 128;
        int r = idx >> 6, c4 = idx & 63;
        float4 v = *(const float4*)&u[(bt * 64 + r) * IN_DIM + c4 * 4];
        *(uint2*)(sm + N0_U_OFF + r * N0_PITCH + c4 * 8) =
            make_uint2(bf2(v.x, v.y), bf2(v.z, v.w));
        float4 wv = *(const float4*)&Wi[r * IN_DIM + c4 * 4];
        *(uint2*)(sm + N0_W_OFF + r * N0_PITCH + c4 * 8) =
            make_uint2(bf2(wv.x, wv.y), bf2(wv.z, wv.w));
    }
    if (t < 64) s_bi[t] = bi[t];
    __syncthreads();

    float acc[8][4];
#pragma unroll
    for (int i = 0; i < 8; i++)
#pragma unroll
        for (int q = 0; q < 4; q++) acc[i][q] = 0.f;

    uint32_t pa = smb + N0_U_OFF +
        (uint32_t)((w * 16 + (lane & 7) + ((lane >> 3) & 1) * 8) * N0_PITCH
                   + (lane >> 4) * 16);
    uint32_t pb = smb + N0_W_OFF +
        (uint32_t)((((lane & 7) + ((lane >> 4) & 1) * 8)) * N0_PITCH
                   + ((lane >> 3) & 1) * 16);
#pragma unroll
    for (int ks = 0; ks < 16; ks++) {
        uint32_t a[4];
        LDM4(a, pa + ks * 32);
#pragma unroll
        for (int np = 0; np < 4; np++) {
            uint32_t b[4];
            LDM4(b, pb + np * 16 * N0_PITCH + ks * 32);
            mma16816(acc[np * 2 + 0], a, b[0], b[1]);
            mma16816(acc[np * 2 + 1], a, b[2], b[3]);
        }
    }

    const int gm = bt * 64 + w * 16 + (lane >> 2);
    const int nb = (lane & 3) * 2;
#pragma unroll
    for (int nt = 0; nt < 8; nt++) {
        int n = nt * 8 + nb;
        float b0 = s_bi[n], b1 = s_bi[n + 1];
        const float* c = acc[nt];
        float2 o0 = make_float2(tanh_fast(c[0] + b0), tanh_fast(c[1] + b1));
        float2 o1 = make_float2(tanh_fast(c[2] + b0), tanh_fast(c[3] + b1));
        *(float2*)&g_net0[gm * 64 + n] = o0;
        *(float2*)&g_net0[(gm + 8) * 64 + n] = o1;
    }
}

// ---------------------------------------------------------------------------
// Kernel 2: main LTC update (R4 structure, verbatim except __fdividef).
// grid (32, 64), 128 threads.
// ---------------------------------------------------------------------------
__global__ void __launch_bounds__(128) ltc_main(
    const float* __restrict__ y,
    const float* __restrict__ tau_raw,
    const float* __restrict__ Wf,  const float* __restrict__ bfw,
    const float* __restrict__ Wr,  const float* __restrict__ brw,
    const float* __restrict__ El,  const float* __restrict__ Elr,
    float* __restrict__ out)
{
    extern __shared__ char sm[];
    const int t     = threadIdx.x;
    const int lane  = t & 31;
    const int warpM = (t >> 5) * 32;
    const int bt    = blockIdx.x;
    const int j     = blockIdx.y;
    const int row0  = bt * 128;

    float* yb   = (float*)(sm + YB_OFF);
    float* s_br = (float*)(sm + BR_OFF);
    float* s_bf = (float*)(sm + BF_OFF);
    float* s_it = (float*)(sm + IT_OFF);
    const uint32_t smb = smem_u32(sm);

    // ---------------- Stage ----------------
#pragma unroll
    for (int i = 0; i < 16; i++) {
        int idx = t + i * 128;
        int r = idx >> 4, c4 = idx & 15;
        float4 v = *(const float4*)&y[(row0 + r) * NTOT + j * 64 + c4 * 4];
        float* yrow = yb + r * 66 + c4 * 4;
        yrow[0] = v.x; yrow[1] = v.y; yrow[2] = v.z; yrow[3] = v.w;
        *(uint2*)(sm + A1_OFF + r * PITCH + c4 * 8) =
            make_uint2(bf2(v.x, v.y), bf2(v.z, v.w));
    }
    if (j > 0) {
#pragma unroll
        for (int i = 0; i < 16; i++) {
            int idx = t + i * 128;
            int r = idx >> 4, c4 = idx & 15;
            float4 v = *(const float4*)&y[(row0 + r) * NTOT + (j - 1) * 64 + c4 * 4];
            *(uint2*)(sm + A0_OFF + r * PITCH + c4 * 8) =
                make_uint2(bf2(v.x, v.y), bf2(v.z, v.w));
        }
    } else {
#pragma unroll
        for (int i = 0; i < 16; i++) {
            int idx = t + i * 128;
            int r = idx >> 4, c4 = idx & 15;
            float4 v = *(const float4*)&g_net0[(row0 + r) * 64 + c4 * 4];
            *(uint2*)(sm + A0_OFF + r * PITCH + c4 * 8) =
                make_uint2(bf2(v.x, v.y), bf2(v.z, v.w));
        }
    }
    {
        const float* wsrc[3] = { Wr + j * 4096, El + j * 4096, Elr + j * 4096 };
        const int    woff[3] = { W1_OFF, W2_OFF, W3_OFF };
#pragma unroll
        for (int wsel = 0; wsel < 3; wsel++) {
#pragma unroll
            for (int i = 0; i < 8; i++) {
                int idx = t + i * 128;
                int o = idx >> 4, c4 = idx & 15;
                float4 v = *(const float4*)&wsrc[wsel][o * 64 + c4 * 4];
                *(uint2*)(sm + woff[wsel] + o * PITCH + c4 * 8) =
                    make_uint2(bf2(v.x, v.y), bf2(v.z, v.w));
            }
        }
        if (j > 0) {
            const float* ws = Wf + (j - 1) * 4096;
#pragma unroll
            for (int i = 0; i < 8; i++) {
                int idx = t + i * 128;
                int o = idx >> 4, c4 = idx & 15;
                float4 v = *(const float4*)&ws[o * 64 + c4 * 4];
                *(uint2*)(sm + W0_OFF + o * PITCH + c4 * 8) =
                    make_uint2(bf2(v.x, v.y), bf2(v.z, v.w));
            }
        }
    }
    if (t < 64) {
        s_br[t] = brw[j * 64 + t];
        if (j > 0) s_bf[t] = bfw[(j - 1) * 64 + t];
        float x  = tau_raw[j * 64 + t];
        float sp = (x > 20.f) ? x : log1pf(expf(x));
        s_it[t]  = 1.0f / (sp + TAU_EPS);
    }
    __syncthreads();

    // ---------------- Phase 1: net_rec / net_fwd ----------------
    float acc[16][4];
#pragma unroll
    for (int i = 0; i < 16; i++)
#pragma unroll
        for (int q = 0; q < 4; q++) acc[i][q] = 0.f;
    gemm32x64(smb + A1_OFF, smb + W1_OFF, acc, lane, warpM);
    tanh_store(acc, s_br, sm + A1_OFF, lane, warpM);

    if (j > 0) {
#pragma unroll
        for (int i = 0; i < 16; i++)
#pragma unroll
            for (int q = 0; q < 4; q++) acc[i][q] = 0.f;
        gemm32x64(smb + A0_OFF, smb + W0_OFF, acc, lane, warpM);
        tanh_store(acc, s_bf, sm + A0_OFF, lane, warpM);
    }
    __syncwarp();   // each warp only touches its own 32 rows of A0/A1

    // ---------------- Phase 2: drive = net_out@El^T + net_rec@Elr^T --------
#pragma unroll
    for (int i = 0; i < 16; i++)
#pragma unroll
        for (int q = 0; q < 4; q++) acc[i][q] = 0.f;
    gemm32x64(smb + A0_OFF, smb + W2_OFF, acc, lane, warpM);
    gemm32x64(smb + A1_OFF, smb + W3_OFF, acc, lane, warpM);

    // ---------------- Epilogue ----------------
    {
        const int gm = warpM + (lane >> 2);
        const int nb = (lane & 3) * 2;
#pragma unroll
        for (int mt = 0; mt < 2; mt++)
#pragma unroll
            for (int nt = 0; nt < 8; nt++) {
                int n = nt * 8 + nb;
                float it0 = s_it[n], it1 = s_it[n + 1];
                const float* c = acc[mt * 8 + nt];
#pragma unroll
                for (int h = 0; h < 2; h++) {
                    int m = gm + mt * 16 + h * 8;
                    float2 no = ubf2(*(const uint32_t*)(sm + A0_OFF + m * PITCH + n * 2));
                    float2 nr = ubf2(*(const uint32_t*)(sm + A1_OFF + m * PITCH + n * 2));
                    float d0 = c[h * 2 + 0], d1 = c[h * 2 + 1];
                    float yv0 = yb[m * 66 + n], yv1 = yb[m * 66 + n + 1];
                    yb[m * 66 + n] = __fdividef(
                        yv0 + DT_C * d0, 1.f + DT_C * (it0 + fabsf(no.x) + fabsf(nr.x)));
                    yb[m * 66 + n + 1] = __fdividef(
                        yv1 + DT_C * d1, 1.f + DT_C * (it1 + fabsf(no.y) + fabsf(nr.y)));
                }
            }
    }
    __syncthreads();

    // ---------------- Coalesced store ----------------
#pragma unroll
    for (int i = 0; i < 16; i++) {
        int idx = t + i * 128;
        int r = idx >> 4, c4 = idx & 15;
        const float* yrow = yb + r * 66 + c4 * 4;
        float4 v = make_float4(yrow[0], yrow[1], yrow[2], yrow[3]);
        *(float4*)&out[(row0 + r) * NTOT + j * 64 + c4 * 4] = v;
    }
}

// ---------------------------------------------------------------------------
extern "C" void kernel_launch(void* const* d_in, const int* in_sizes, int n_in,
                              void* d_out, int out_size) {
    const float* y   = (const float*)d_in[0];
    const float* u_t = (const float*)d_in[1];
    const float* tau = (const float*)d_in[2];
    const float* Wi  = (const float*)d_in[3];
    const float* bi  = (const float*)d_in[4];
    const float* Wf  = (const float*)d_in[5];
    const float* bfw = (const float*)d_in[6];
    const float* Wr  = (const float*)d_in[7];
    const float* brw = (const float*)d_in[8];
    const float* El  = (const float*)d_in[9];
    const float* Elr = (const float*)d_in[10];
    float* out = (float*)d_out;

    cudaFuncSetAttribute(net0_kernel, cudaFuncAttributeMaxDynamicSharedMemorySize,
                         N0_SMEM);
    cudaFuncSetAttribute(ltc_main, cudaFuncAttributeMaxDynamicSharedMemorySize,
                         SMEM_TOTAL);

    net0_kernel<<<BATCH / 64, 128, N0_SMEM>>>(u_t, Wi, bi);
    ltc_main<<<dim3(BATCH / 128, NB), 128, SMEM_TOTAL>>>(
        y, tau, Wf, bfw, Wr, brw, El, Elr, out);
}

// round 8
// speedup vs baseline: 1.5959x; 1.1735x over previous
#include <cuda_runtime.h>
#include <cuda_bf16.h>
#include <cstdint>

#define BATCH   4096
#define NB      64
#define IN_DIM  256
#define NTOT    4096
#define DT_C    0.05f
#define TAU_EPS 1e-6f

// bf16 tile row pitch: 72 elems = 144 bytes (odd 16B-groups -> conflict-free ldmatrix)
#define PITCH   144

// ---------------- SMEM layout (byte offsets) ----------------
#define A0_OFF  0                       // 128 x 64 bf16 (y_prev | u chunk)
#define A1_OFF  18432                   // 128 x 64 bf16 (y_cur)
#define W0_OFF  36864                   // W_fwd[j-1] | W_in chunk
#define W1_OFF  46080                   // W_rec[j]
#define W2_OFF  55296                   // E_l[j]
#define W3_OFF  64512                   // E_l_r[j]
#define YB_OFF  73728                   // 128 x 66 fp32 exact y -> y_new
#define BR_OFF  (YB_OFF + 128*66*4)     // 107520
#define BF_OFF  (BR_OFF + 256)
#define IT_OFF  (BF_OFF + 256)
#define SMEM_TOTAL (IT_OFF + 256)       // 108288 bytes -> 2 CTAs/SM

// ---------------------------------------------------------------------------
// helpers
// ---------------------------------------------------------------------------
__device__ __forceinline__ uint32_t smem_u32(const void* p) {
    uint32_t a;
    asm("{ .reg .u64 t; cvta.to.shared.u64 t, %1; cvt.u32.u64 %0, t; }"
        : "=r"(a) : "l"(p));
    return a;
}
__device__ __forceinline__ float tanh_fast(float x) {
    float r; asm("tanh.approx.f32 %0, %1;" : "=f"(r) : "f"(x)); return r;
}
__device__ __forceinline__ uint32_t bf2(float lo, float hi) {
    uint32_t r;
    asm("cvt.rn.bf16x2.f32 %0, %1, %2;" : "=r"(r) : "f"(hi), "f"(lo));
    return r;
}
__device__ __forceinline__ float2 ubf2(uint32_t v) {
    __nv_bfloat162 b = *reinterpret_cast<__nv_bfloat162*>(&v);
    return __bfloat1622float2(b);
}

#define LDM4(r, addr) \
    asm volatile("ldmatrix.sync.aligned.m8n8.x4.shared.b16 {%0,%1,%2,%3}, [%4];" \
        : "=r"((r)[0]), "=r"((r)[1]), "=r"((r)[2]), "=r"((r)[3]) : "r"(addr))

__device__ __forceinline__ void mma16816(float* c, const uint32_t* a,
                                         uint32_t b0, uint32_t b1) {
    asm volatile(
        "mma.sync.aligned.m16n8k16.row.col.f32.bf16.bf16.f32 "
        "{%0,%1,%2,%3}, {%4,%5,%6,%7}, {%8,%9}, {%0,%1,%2,%3};"
        : "+f"(c[0]), "+f"(c[1]), "+f"(c[2]), "+f"(c[3])
        : "r"(a[0]), "r"(a[1]), "r"(a[2]), "r"(a[3]), "r"(b0), "r"(b1));
}

// Warp computes C[32 x 64] += A_smem[32 x 64] * W_smem[64 x 64]^T
__device__ __forceinline__ void gemm32x64(uint32_t abase, uint32_t wbase,
                                          float acc[16][4], int lane, int warpM)
{
    uint32_t pa = abase + (uint32_t)((warpM + (lane & 7) + ((lane >> 3) & 1) * 8) * PITCH
                                     + ((lane >> 4) * 8) * 2);
    uint32_t pb = wbase + (uint32_t)((((lane & 7) + ((lane >> 4) & 1) * 8)) * PITCH
                                     + (((lane >> 3) & 1) * 8) * 2);
#pragma unroll
    for (int ks = 0; ks < 4; ks++) {
        uint32_t a0[4], a1[4];
        LDM4(a0, pa + ks * 32);
        LDM4(a1, pa + 16 * PITCH + ks * 32);
#pragma unroll
        for (int np = 0; np < 4; np++) {
            uint32_t b[4];
            LDM4(b, pb + np * 16 * PITCH + ks * 32);
            mma16816(acc[np * 2 + 0],     a0, b[0], b[1]);
            mma16816(acc[np * 2 + 1],     a0, b[2], b[3]);
            mma16816(acc[8 + np * 2 + 0], a1, b[0], b[1]);
            mma16816(acc[8 + np * 2 + 1], a1, b[2], b[3]);
        }
    }
}

// Warp computes C[32 x 64] += A_regs * W_smem^T ; A = packed bf16x2 fragments
__device__ __forceinline__ void gemm32x64_reg(uint32_t wbase,
                                              const uint32_t lo[2][8],
                                              const uint32_t hi[2][8],
                                              float acc[16][4], int lane)
{
    uint32_t pb = wbase + (uint32_t)((((lane & 7) + ((lane >> 4) & 1) * 8)) * PITCH
                                     + (((lane >> 3) & 1) * 8) * 2);
#pragma unroll
    for (int ks = 0; ks < 4; ks++) {
#pragma unroll
        for (int np = 0; np < 4; np++) {
            uint32_t b[4];
            LDM4(b, pb + np * 16 * PITCH + ks * 32);
#pragma unroll
            for (int mt = 0; mt < 2; mt++) {
                uint32_t a[4] = { lo[mt][2 * ks], hi[mt][2 * ks],
                                  lo[mt][2 * ks + 1], hi[mt][2 * ks + 1] };
                mma16816(acc[mt * 8 + np * 2 + 0], a, b[0], b[1]);
                mma16816(acc[mt * 8 + np * 2 + 1], a, b[2], b[3]);
            }
        }
    }
}

// tanh(acc + bias) -> packed bf16x2 fragments in registers
__device__ __forceinline__ void pack_tanh(const float acc[16][4], const float* bias,
                                          uint32_t lo[2][8], uint32_t hi[2][8],
                                          int lane)
{
    const int nb = (lane & 3) * 2;
#pragma unroll
    for (int mt = 0; mt < 2; mt++)
#pragma unroll
        for (int nt = 0; nt < 8; nt++) {
            const float* c = acc[mt * 8 + nt];
            float b0 = bias[nt * 8 + nb], b1 = bias[nt * 8 + nb + 1];
            lo[mt][nt] = bf2(tanh_fast(c[0] + b0), tanh_fast(c[1] + b1));
            hi[mt][nt] = bf2(tanh_fast(c[2] + b0), tanh_fast(c[3] + b1));
        }
}

__device__ __forceinline__ void zero_acc(float acc[16][4]) {
#pragma unroll
    for (int i = 0; i < 16; i++)
#pragma unroll
        for (int q = 0; q < 4; q++) acc[i][q] = 0.f;
}

__device__ __forceinline__ void stage128(char* dst, const float* __restrict__ src,
                                         int srcPitch, int t)
{
#pragma unroll
    for (int i = 0; i < 16; i++) {
        int idx = t + i * 128;
        int r = idx >> 4, c4 = idx & 15;
        float4 v = *(const float4*)&src[r * srcPitch + c4 * 4];
        *(uint2*)(dst + r * PITCH + c4 * 8) = make_uint2(bf2(v.x, v.y), bf2(v.z, v.w));
    }
}
__device__ __forceinline__ void stage64(char* dst, const float* __restrict__ src,
                                        int srcPitch, int t)
{
#pragma unroll
    for (int i = 0; i < 8; i++) {
        int idx = t + i * 128;
        int o = idx >> 4, c4 = idx & 15;
        float4 v = *(const float4*)&src[o * srcPitch + c4 * 4];
        *(uint2*)(dst + o * PITCH + c4 * 8) = make_uint2(bf2(v.x, v.y), bf2(v.z, v.w));
    }
}

// ---------------------------------------------------------------------------
// Single fused kernel. grid (32 batch tiles, 64 blocks j), 128 threads.
// ---------------------------------------------------------------------------
__global__ void __launch_bounds__(128) ltc_main(
    const float* __restrict__ y,
    const float* __restrict__ u,
    const float* __restrict__ tau_raw,
    const float* __restrict__ Wi,  const float* __restrict__ bi,
    const float* __restrict__ Wf,  const float* __restrict__ bfw,
    const float* __restrict__ Wr,  const float* __restrict__ brw,
    const float* __restrict__ El,  const float* __restrict__ Elr,
    float* __restrict__ out)
{
    extern __shared__ char sm[];
    const int t     = threadIdx.x;
    const int lane  = t & 31;
    const int warpM = (t >> 5) * 32;
    const int bt    = blockIdx.x;
    const int j     = blockIdx.y;
    const int row0  = bt * 128;

    float* yb   = (float*)(sm + YB_OFF);
    float* s_br = (float*)(sm + BR_OFF);
    float* s_bf = (float*)(sm + BF_OFF);
    float* s_it = (float*)(sm + IT_OFF);
    const uint32_t smb = smem_u32(sm);

    // ---------------- Stage: y tile (fp32 exact + bf16), weights ----------
#pragma unroll
    for (int i = 0; i < 16; i++) {
        int idx = t + i * 128;
        int r = idx >> 4, c4 = idx & 15;
        float4 v = *(const float4*)&y[(row0 + r) * NTOT + j * 64 + c4 * 4];
        float* yrow = yb + r * 66 + c4 * 4;
        yrow[0] = v.x; yrow[1] = v.y; yrow[2] = v.z; yrow[3] = v.w;
        *(uint2*)(sm + A1_OFF + r * PITCH + c4 * 8) =
            make_uint2(bf2(v.x, v.y), bf2(v.z, v.w));
    }
    if (j > 0) {
        stage128(sm + A0_OFF, y + (size_t)row0 * NTOT + (j - 1) * 64, NTOT, t);
        stage64(sm + W0_OFF, Wf + (j - 1) * 4096, 64, t);
    }
    stage64(sm + W1_OFF, Wr  + j * 4096, 64, t);
    stage64(sm + W2_OFF, El  + j * 4096, 64, t);
    stage64(sm + W3_OFF, Elr + j * 4096, 64, t);
    if (t < 64) {
        s_br[t] = brw[j * 64 + t];
        s_bf[t] = (j > 0) ? bfw[(j - 1) * 64 + t] : bi[t];
        float x  = tau_raw[j * 64 + t];
        float sp = (x > 20.f) ? x : log1pf(expf(x));
        s_it[t]  = 1.0f / (sp + TAU_EPS);
    }
    __syncthreads();

    float acc[16][4];
    uint32_t nr_lo[2][8], nr_hi[2][8];   // net_rec packed bf16x2 fragments
    uint32_t no_lo[2][8], no_hi[2][8];   // net_out packed bf16x2 fragments

    // ---------------- Phase 1a: net_rec = tanh(y_cur @ Wr^T + br) ----------
    zero_acc(acc);
    gemm32x64(smb + A1_OFF, smb + W1_OFF, acc, lane, warpM);
    pack_tanh(acc, s_br, nr_lo, nr_hi, lane);

    // ---------------- Phase 1b: net_out ------------------------------------
    zero_acc(acc);
    if (j > 0) {
        gemm32x64(smb + A0_OFF, smb + W0_OFF, acc, lane, warpM);
    } else {
        // net0 = u_t @ W_in^T over K=256 in 4 staged chunks (block-uniform)
        for (int kc = 0; kc < 4; kc++) {
            __syncthreads();
            stage128(sm + A0_OFF, u + (size_t)row0 * IN_DIM + kc * 64, IN_DIM, t);
            stage64(sm + W0_OFF, Wi + kc * 64, IN_DIM, t);
            __syncthreads();
            gemm32x64(smb + A0_OFF, smb + W0_OFF, acc, lane, warpM);
        }
    }
    pack_tanh(acc, s_bf, no_lo, no_hi, lane);

    // ---------------- Phase 2: drive = net_out@El^T + net_rec@Elr^T --------
    zero_acc(acc);
    gemm32x64_reg(smb + W2_OFF, no_lo, no_hi, acc, lane);
    gemm32x64_reg(smb + W3_OFF, nr_lo, nr_hi, acc, lane);

    // ---------------- Epilogue: combine in YB (nets from registers) --------
    {
        const int gm = warpM + (lane >> 2);
        const int nb = (lane & 3) * 2;
#pragma unroll
        for (int mt = 0; mt < 2; mt++)
#pragma unroll
            for (int nt = 0; nt < 8; nt++) {
                int n = nt * 8 + nb;
                float it0 = s_it[n], it1 = s_it[n + 1];
                float2 no0 = ubf2(no_lo[mt][nt]), no1 = ubf2(no_hi[mt][nt]);
                float2 nr0 = ubf2(nr_lo[mt][nt]), nr1 = ubf2(nr_hi[mt][nt]);
                const float* c = acc[mt * 8 + nt];
                int m0 = gm + mt * 16;
                float2 ya = *(const float2*)&yb[m0 * 66 + n];
                float2 yc = *(const float2*)&yb[(m0 + 8) * 66 + n];
                float2 o0, o1;
                o0.x = __fdividef(ya.x + DT_C * c[0],
                                  1.f + DT_C * (it0 + fabsf(no0.x) + fabsf(nr0.x)));
                o0.y = __fdividef(ya.y + DT_C * c[1],
                                  1.f + DT_C * (it1 + fabsf(no0.y) + fabsf(nr0.y)));
                o1.x = __fdividef(yc.x + DT_C * c[2],
                                  1.f + DT_C * (it0 + fabsf(no1.x) + fabsf(nr1.x)));
                o1.y = __fdividef(yc.y + DT_C * c[3],
                                  1.f + DT_C * (it1 + fabsf(no1.y) + fabsf(nr1.y)));
                *(float2*)&yb[m0 * 66 + n] = o0;
                *(float2*)&yb[(m0 + 8) * 66 + n] = o1;
            }
    }
    __syncthreads();

    // ---------------- Coalesced store ----------------
#pragma unroll
    for (int i = 0; i < 16; i++) {
        int idx = t + i * 128;
        int r = idx >> 4, c4 = idx & 15;
        const float* yrow = yb + r * 66 + c4 * 4;
        float4 v = make_float4(yrow[0], yrow[1], yrow[2], yrow[3]);
        *(float4*)&out[(row0 + r) * NTOT + j * 64 + c4 * 4] = v;
    }
}

// ---------------------------------------------------------------------------
extern "C" void kernel_launch(void* const* d_in, const int* in_sizes, int n_in,
                              void* d_out, int out_size) {
    const float* y   = (const float*)d_in[0];
    const float* u_t = (const float*)d_in[1];
    const float* tau = (const float*)d_in[2];
    const float* Wi  = (const float*)d_in[3];
    const float* bi  = (const float*)d_in[4];
    const float* Wf  = (const float*)d_in[5];
    const float* bfw = (const float*)d_in[6];
    const float* Wr  = (const float*)d_in[7];
    const float* brw = (const float*)d_in[8];
    const float* El  = (const float*)d_in[9];
    const float* Elr = (const float*)d_in[10];
    float* out = (float*)d_out;

    cudaFuncSetAttribute(ltc_main, cudaFuncAttributeMaxDynamicSharedMemorySize,
                         SMEM_TOTAL);

    ltc_main<<<dim3(BATCH / 128, NB), 128, SMEM_TOTAL>>>(
        y, u_t, tau, Wi, bi, Wf, bfw, Wr, brw, El, Elr, out);
}

// round 9
// speedup vs baseline: 1.7727x; 1.1108x over previous
#include <cuda_runtime.h>
#include <cuda_bf16.h>
#include <cstdint>

#define BATCH   4096
#define NB      64
#define IN_DIM  256
#define NTOT    4096
#define DT_C    0.05f
#define TAU_EPS 1e-6f

// bf16 tile row pitch: 72 elems = 144 bytes (odd 16B-groups -> conflict-free ldmatrix)
#define PITCH   144

// ---------------- SMEM layout (byte offsets) ----------------
#define A0_OFF  0                       // 128 x 64 bf16 (y_prev | u chunk)
#define A1_OFF  18432                   // 128 x 64 bf16 (y_cur)
#define W0_OFF  36864                   // W_fwd[j-1] | W_in chunk
#define W1_OFF  46080                   // W_rec[j]
#define W2_OFF  55296                   // E_l[j]
#define W3_OFF  64512                   // E_l_r[j]
#define YB_OFF  73728                   // 128 x 66 fp32 exact y (read-only after stage)
#define BR_OFF  (YB_OFF + 128*66*4)     // 107520
#define BF_OFF  (BR_OFF + 256)
#define IT_OFF  (BF_OFF + 256)
#define SMEM_TOTAL (IT_OFF + 256)       // 108288 bytes -> 2 CTAs/SM

// ---------------------------------------------------------------------------
// helpers
// ---------------------------------------------------------------------------
__device__ __forceinline__ uint32_t smem_u32(const void* p) {
    uint32_t a;
    asm("{ .reg .u64 t; cvta.to.shared.u64 t, %1; cvt.u32.u64 %0, t; }"
        : "=r"(a) : "l"(p));
    return a;
}
__device__ __forceinline__ float tanh_fast(float x) {
    float r; asm("tanh.approx.f32 %0, %1;" : "=f"(r) : "f"(x)); return r;
}
__device__ __forceinline__ uint32_t bf2(float lo, float hi) {
    uint32_t r;
    asm("cvt.rn.bf16x2.f32 %0, %1, %2;" : "=r"(r) : "f"(hi), "f"(lo));
    return r;
}
__device__ __forceinline__ float2 ubf2(uint32_t v) {
    __nv_bfloat162 b = *reinterpret_cast<__nv_bfloat162*>(&v);
    return __bfloat1622float2(b);
}

#define LDM4(r, addr) \
    asm volatile("ldmatrix.sync.aligned.m8n8.x4.shared.b16 {%0,%1,%2,%3}, [%4];" \
        : "=r"((r)[0]), "=r"((r)[1]), "=r"((r)[2]), "=r"((r)[3]) : "r"(addr))

__device__ __forceinline__ void mma16816(float* c, const uint32_t* a,
                                         uint32_t b0, uint32_t b1) {
    asm volatile(
        "mma.sync.aligned.m16n8k16.row.col.f32.bf16.bf16.f32 "
        "{%0,%1,%2,%3}, {%4,%5,%6,%7}, {%8,%9}, {%0,%1,%2,%3};"
        : "+f"(c[0]), "+f"(c[1]), "+f"(c[2]), "+f"(c[3])
        : "r"(a[0]), "r"(a[1]), "r"(a[2]), "r"(a[3]), "r"(b0), "r"(b1));
}

// Warp computes C[32 x 64] += A_smem[32 x 64] * W_smem[64 x 64]^T
__device__ __forceinline__ void gemm32x64(uint32_t abase, uint32_t wbase,
                                          float acc[16][4], int lane, int warpM)
{
    uint32_t pa = abase + (uint32_t)((warpM + (lane & 7) + ((lane >> 3) & 1) * 8) * PITCH
                                     + ((lane >> 4) * 8) * 2);
    uint32_t pb = wbase + (uint32_t)((((lane & 7) + ((lane >> 4) & 1) * 8)) * PITCH
                                     + (((lane >> 3) & 1) * 8) * 2);
#pragma unroll
    for (int ks = 0; ks < 4; ks++) {
        uint32_t a0[4], a1[4];
        LDM4(a0, pa + ks * 32);
        LDM4(a1, pa + 16 * PITCH + ks * 32);
#pragma unroll
        for (int np = 0; np < 4; np++) {
            uint32_t b[4];
            LDM4(b, pb + np * 16 * PITCH + ks * 32);
            mma16816(acc[np * 2 + 0],     a0, b[0], b[1]);
            mma16816(acc[np * 2 + 1],     a0, b[2], b[3]);
            mma16816(acc[8 + np * 2 + 0], a1, b[0], b[1]);
            mma16816(acc[8 + np * 2 + 1], a1, b[2], b[3]);
        }
    }
}

// Warp computes C[32 x 64] += A_regs * W_smem^T ; A = packed bf16x2 fragments
__device__ __forceinline__ void gemm32x64_reg(uint32_t wbase,
                                              const uint32_t lo[2][8],
                                              const uint32_t hi[2][8],
                                              float acc[16][4], int lane)
{
    uint32_t pb = wbase + (uint32_t)((((lane & 7) + ((lane >> 4) & 1) * 8)) * PITCH
                                     + (((lane >> 3) & 1) * 8) * 2);
#pragma unroll
    for (int ks = 0; ks < 4; ks++) {
#pragma unroll
        for (int np = 0; np < 4; np++) {
            uint32_t b[4];
            LDM4(b, pb + np * 16 * PITCH + ks * 32);
#pragma unroll
            for (int mt = 0; mt < 2; mt++) {
                uint32_t a[4] = { lo[mt][2 * ks], hi[mt][2 * ks],
                                  lo[mt][2 * ks + 1], hi[mt][2 * ks + 1] };
                mma16816(acc[mt * 8 + np * 2 + 0], a, b[0], b[1]);
                mma16816(acc[mt * 8 + np * 2 + 1], a, b[2], b[3]);
            }
        }
    }
}

// tanh(acc + bias) -> packed bf16x2 fragments in registers
__device__ __forceinline__ void pack_tanh(const float acc[16][4], const float* bias,
                                          uint32_t lo[2][8], uint32_t hi[2][8],
                                          int lane)
{
    const int nb = (lane & 3) * 2;
#pragma unroll
    for (int mt = 0; mt < 2; mt++)
#pragma unroll
        for (int nt = 0; nt < 8; nt++) {
            const float* c = acc[mt * 8 + nt];
            float b0 = bias[nt * 8 + nb], b1 = bias[nt * 8 + nb + 1];
            lo[mt][nt] = bf2(tanh_fast(c[0] + b0), tanh_fast(c[1] + b1));
            hi[mt][nt] = bf2(tanh_fast(c[2] + b0), tanh_fast(c[3] + b1));
        }
}

__device__ __forceinline__ void zero_acc(float acc[16][4]) {
#pragma unroll
    for (int i = 0; i < 16; i++)
#pragma unroll
        for (int q = 0; q < 4; q++) acc[i][q] = 0.f;
}

__device__ __forceinline__ void stage128(char* dst, const float* __restrict__ src,
                                         int srcPitch, int t)
{
#pragma unroll
    for (int i = 0; i < 16; i++) {
        int idx = t + i * 128;
        int r = idx >> 4, c4 = idx & 15;
        float4 v = *(const float4*)&src[r * srcPitch + c4 * 4];
        *(uint2*)(dst + r * PITCH + c4 * 8) = make_uint2(bf2(v.x, v.y), bf2(v.z, v.w));
    }
}
__device__ __forceinline__ void stage64(char* dst, const float* __restrict__ src,
                                        int srcPitch, int t)
{
#pragma unroll
    for (int i = 0; i < 8; i++) {
        int idx = t + i * 128;
        int o = idx >> 4, c4 = idx & 15;
        float4 v = *(const float4*)&src[o * srcPitch + c4 * 4];
        *(uint2*)(dst + o * PITCH + c4 * 8) = make_uint2(bf2(v.x, v.y), bf2(v.z, v.w));
    }
}

// ---------------------------------------------------------------------------
// Single fused kernel. grid (32 batch tiles, 64 blocks j), 128 threads.
// ---------------------------------------------------------------------------
__global__ void __launch_bounds__(128) ltc_main(
    const float* __restrict__ y,
    const float* __restrict__ u,
    const float* __restrict__ tau_raw,
    const float* __restrict__ Wi,  const float* __restrict__ bi,
    const float* __restrict__ Wf,  const float* __restrict__ bfw,
    const float* __restrict__ Wr,  const float* __restrict__ brw,
    const float* __restrict__ El,  const float* __restrict__ Elr,
    float* __restrict__ out)
{
    extern __shared__ char sm[];
    const int t     = threadIdx.x;
    const int lane  = t & 31;
    const int warpM = (t >> 5) * 32;
    const int bt    = blockIdx.x;
    const int j     = blockIdx.y;
    const int row0  = bt * 128;

    float* yb   = (float*)(sm + YB_OFF);
    float* s_br = (float*)(sm + BR_OFF);
    float* s_bf = (float*)(sm + BF_OFF);
    float* s_it = (float*)(sm + IT_OFF);
    const uint32_t smb = smem_u32(sm);

    // ---------------- Stage: y tile (fp32 exact + bf16), weights ----------
#pragma unroll
    for (int i = 0; i < 16; i++) {
        int idx = t + i * 128;
        int r = idx >> 4, c4 = idx & 15;
        float4 v = *(const float4*)&y[(row0 + r) * NTOT + j * 64 + c4 * 4];
        float* yrow = yb + r * 66 + c4 * 4;
        yrow[0] = v.x; yrow[1] = v.y; yrow[2] = v.z; yrow[3] = v.w;
        *(uint2*)(sm + A1_OFF + r * PITCH + c4 * 8) =
            make_uint2(bf2(v.x, v.y), bf2(v.z, v.w));
    }
    if (j > 0) {
        stage128(sm + A0_OFF, y + (size_t)row0 * NTOT + (j - 1) * 64, NTOT, t);
        stage64(sm + W0_OFF, Wf + (j - 1) * 4096, 64, t);
    }
    stage64(sm + W1_OFF, Wr  + j * 4096, 64, t);
    stage64(sm + W2_OFF, El  + j * 4096, 64, t);
    stage64(sm + W3_OFF, Elr + j * 4096, 64, t);
    if (t < 64) {
        s_br[t] = brw[j * 64 + t];
        s_bf[t] = (j > 0) ? bfw[(j - 1) * 64 + t] : bi[t];
        float x  = tau_raw[j * 64 + t];
        float sp = (x > 20.f) ? x : log1pf(expf(x));
        s_it[t]  = 1.0f / (sp + TAU_EPS);
    }
    __syncthreads();

    float acc[16][4];
    uint32_t nr_lo[2][8], nr_hi[2][8];   // net_rec packed bf16x2 fragments
    uint32_t no_lo[2][8], no_hi[2][8];   // net_out packed bf16x2 fragments

    // ---------------- Phase 1a: net_rec = tanh(y_cur @ Wr^T + br) ----------
    zero_acc(acc);
    gemm32x64(smb + A1_OFF, smb + W1_OFF, acc, lane, warpM);
    pack_tanh(acc, s_br, nr_lo, nr_hi, lane);

    // ---------------- Phase 1b: net_out ------------------------------------
    zero_acc(acc);
    if (j > 0) {
        gemm32x64(smb + A0_OFF, smb + W0_OFF, acc, lane, warpM);
    } else {
        // net0 = u_t @ W_in^T over K=256 in 4 staged chunks (block-uniform)
        for (int kc = 0; kc < 4; kc++) {
            __syncthreads();
            stage128(sm + A0_OFF, u + (size_t)row0 * IN_DIM + kc * 64, IN_DIM, t);
            stage64(sm + W0_OFF, Wi + kc * 64, IN_DIM, t);
            __syncthreads();
            gemm32x64(smb + A0_OFF, smb + W0_OFF, acc, lane, warpM);
        }
    }
    pack_tanh(acc, s_bf, no_lo, no_hi, lane);

    // ---------------- Phase 2: drive = net_out@El^T + net_rec@Elr^T --------
    zero_acc(acc);
    gemm32x64_reg(smb + W2_OFF, no_lo, no_hi, acc, lane);
    gemm32x64_reg(smb + W3_OFF, nr_lo, nr_hi, acc, lane);

    // ---------------- Epilogue: combine + direct fragment stores -----------
    {
        const int gm = warpM + (lane >> 2);
        const int nb = (lane & 3) * 2;
#pragma unroll
        for (int mt = 0; mt < 2; mt++)
#pragma unroll
            for (int nt = 0; nt < 8; nt++) {
                int n = nt * 8 + nb;
                float it0 = s_it[n], it1 = s_it[n + 1];
                float2 no0 = ubf2(no_lo[mt][nt]), no1 = ubf2(no_hi[mt][nt]);
                float2 nr0 = ubf2(nr_lo[mt][nt]), nr1 = ubf2(nr_hi[mt][nt]);
                const float* c = acc[mt * 8 + nt];
                int m0 = gm + mt * 16;
                float2 ya = *(const float2*)&yb[m0 * 66 + n];
                float2 yc = *(const float2*)&yb[(m0 + 8) * 66 + n];
                float2 o0, o1;
                o0.x = __fdividef(ya.x + DT_C * c[0],
                                  1.f + DT_C * (it0 + fabsf(no0.x) + fabsf(nr0.x)));
                o0.y = __fdividef(ya.y + DT_C * c[1],
                                  1.f + DT_C * (it1 + fabsf(no0.y) + fabsf(nr0.y)));
                o1.x = __fdividef(yc.x + DT_C * c[2],
                                  1.f + DT_C * (it0 + fabsf(no1.x) + fabsf(nr1.x)));
                o1.y = __fdividef(yc.y + DT_C * c[3],
                                  1.f + DT_C * (it1 + fabsf(no1.y) + fabsf(nr1.y)));
                *(float2*)&out[(size_t)(row0 + m0) * NTOT + j * 64 + n] = o0;
                *(float2*)&out[(size_t)(row0 + m0 + 8) * NTOT + j * 64 + n] = o1;
            }
    }
}

// ---------------------------------------------------------------------------
extern "C" void kernel_launch(void* const* d_in, const int* in_sizes, int n_in,
                              void* d_out, int out_size) {
    const float* y   = (const float*)d_in[0];
    const float* u_t = (const float*)d_in[1];
    const float* tau = (const float*)d_in[2];
    const float* Wi  = (const float*)d_in[3];
    const float* bi  = (const float*)d_in[4];
    const float* Wf  = (const float*)d_in[5];
    const float* bfw = (const float*)d_in[6];
    const float* Wr  = (const float*)d_in[7];
    const float* brw = (const float*)d_in[8];
    const float* El  = (const float*)d_in[9];
    const float* Elr = (const float*)d_in[10];
    float* out = (float*)d_out;

    cudaFuncSetAttribute(ltc_main, cudaFuncAttributeMaxDynamicSharedMemorySize,
                         SMEM_TOTAL);

    ltc_main<<<dim3(BATCH / 128, NB), 128, SMEM_TOTAL>>>(
        y, u_t, tau, Wi, bi, Wf, bfw, Wr, brw, El, Elr, out);
}

// round 10
// speedup vs baseline: 2.1060x; 1.1880x over previous
#include <cuda_runtime.h>
#include <cuda_bf16.h>
#include <cstdint>

#define BATCH   4096
#define NB      64
#define IN_DIM  256
#define NTOT    4096
#define DT_C    0.05f
#define TAU_EPS 1e-6f

// bf16 tile row pitch: 72 elems = 144 bytes (odd 16B-groups -> conflict-free ldmatrix)
#define PITCH   144

// ---------------- SMEM layout (byte offsets) ----------------
#define A0_OFF  0                       // 128 x 64 bf16 (y_prev | u chunk)
#define A1_OFF  18432                   // 128 x 64 bf16 (y_cur)
#define W0_OFF  36864                   // W_fwd[j-1] | W_in chunk
#define W1_OFF  46080                   // W_rec[j]
#define W2_OFF  55296                   // E_l[j]
#define W3_OFF  64512                   // E_l_r[j]
#define BR_OFF  73728
#define BF_OFF  (BR_OFF + 256)
#define IT_OFF  (BF_OFF + 256)
#define SMEM_TOTAL (IT_OFF + 256)       // 74496 B; occupancy pinned to 2 CTAs/SM

// ---------------------------------------------------------------------------
// helpers
// ---------------------------------------------------------------------------
__device__ __forceinline__ uint32_t smem_u32(const void* p) {
    uint32_t a;
    asm("{ .reg .u64 t; cvta.to.shared.u64 t, %1; cvt.u32.u64 %0, t; }"
        : "=r"(a) : "l"(p));
    return a;
}
__device__ __forceinline__ float tanh_fast(float x) {
    float r; asm("tanh.approx.f32 %0, %1;" : "=f"(r) : "f"(x)); return r;
}
__device__ __forceinline__ uint32_t bf2(float lo, float hi) {
    uint32_t r;
    asm("cvt.rn.bf16x2.f32 %0, %1, %2;" : "=r"(r) : "f"(hi), "f"(lo));
    return r;
}
__device__ __forceinline__ float2 ubf2(uint32_t v) {
    __nv_bfloat162 b = *reinterpret_cast<__nv_bfloat162*>(&v);
    return __bfloat1622float2(b);
}

#define LDM4(r, addr) \
    asm volatile("ldmatrix.sync.aligned.m8n8.x4.shared.b16 {%0,%1,%2,%3}, [%4];" \
        : "=r"((r)[0]), "=r"((r)[1]), "=r"((r)[2]), "=r"((r)[3]) : "r"(addr))

__device__ __forceinline__ void mma16816(float* c, const uint32_t* a,
                                         uint32_t b0, uint32_t b1) {
    asm volatile(
        "mma.sync.aligned.m16n8k16.row.col.f32.bf16.bf16.f32 "
        "{%0,%1,%2,%3}, {%4,%5,%6,%7}, {%8,%9}, {%0,%1,%2,%3};"
        : "+f"(c[0]), "+f"(c[1]), "+f"(c[2]), "+f"(c[3])
        : "r"(a[0]), "r"(a[1]), "r"(a[2]), "r"(a[3]), "r"(b0), "r"(b1));
}

// Warp computes C[32 x 64] += A_smem[32 x 64] * W_smem[64 x 64]^T
__device__ __forceinline__ void gemm32x64(uint32_t abase, uint32_t wbase,
                                          float acc[16][4], int lane, int warpM)
{
    uint32_t pa = abase + (uint32_t)((warpM + (lane & 7) + ((lane >> 3) & 1) * 8) * PITCH
                                     + ((lane >> 4) * 8) * 2);
    uint32_t pb = wbase + (uint32_t)((((lane & 7) + ((lane >> 4) & 1) * 8)) * PITCH
                                     + (((lane >> 3) & 1) * 8) * 2);
#pragma unroll
    for (int ks = 0; ks < 4; ks++) {
        uint32_t a0[4], a1[4];
        LDM4(a0, pa + ks * 32);
        LDM4(a1, pa + 16 * PITCH + ks * 32);
#pragma unroll
        for (int np = 0; np < 4; np++) {
            uint32_t b[4];
            LDM4(b, pb + np * 16 * PITCH + ks * 32);
            mma16816(acc[np * 2 + 0],     a0, b[0], b[1]);
            mma16816(acc[np * 2 + 1],     a0, b[2], b[3]);
            mma16816(acc[8 + np * 2 + 0], a1, b[0], b[1]);
            mma16816(acc[8 + np * 2 + 1], a1, b[2], b[3]);
        }
    }
}

// Warp computes C[32 x 64] += A_regs * W_smem^T ; A = packed bf16x2 fragments
__device__ __forceinline__ void gemm32x64_reg(uint32_t wbase,
                                              const uint32_t lo[2][8],
                                              const uint32_t hi[2][8],
                                              float acc[16][4], int lane)
{
    uint32_t pb = wbase + (uint32_t)((((lane & 7) + ((lane >> 4) & 1) * 8)) * PITCH
                                     + (((lane >> 3) & 1) * 8) * 2);
#pragma unroll
    for (int ks = 0; ks < 4; ks++) {
#pragma unroll
        for (int np = 0; np < 4; np++) {
            uint32_t b[4];
            LDM4(b, pb + np * 16 * PITCH + ks * 32);
#pragma unroll
            for (int mt = 0; mt < 2; mt++) {
                uint32_t a[4] = { lo[mt][2 * ks], hi[mt][2 * ks],
                                  lo[mt][2 * ks + 1], hi[mt][2 * ks + 1] };
                mma16816(acc[mt * 8 + np * 2 + 0], a, b[0], b[1]);
                mma16816(acc[mt * 8 + np * 2 + 1], a, b[2], b[3]);
            }
        }
    }
}

// tanh(acc + bias) -> packed bf16x2 fragments in registers
__device__ __forceinline__ void pack_tanh(const float acc[16][4], const float* bias,
                                          uint32_t lo[2][8], uint32_t hi[2][8],
                                          int lane)
{
    const int nb = (lane & 3) * 2;
#pragma unroll
    for (int mt = 0; mt < 2; mt++)
#pragma unroll
        for (int nt = 0; nt < 8; nt++) {
            const float* c = acc[mt * 8 + nt];
            float b0 = bias[nt * 8 + nb], b1 = bias[nt * 8 + nb + 1];
            lo[mt][nt] = bf2(tanh_fast(c[0] + b0), tanh_fast(c[1] + b1));
            hi[mt][nt] = bf2(tanh_fast(c[2] + b0), tanh_fast(c[3] + b1));
        }
}

__device__ __forceinline__ void zero_acc(float acc[16][4]) {
#pragma unroll
    for (int i = 0; i < 16; i++)
#pragma unroll
        for (int q = 0; q < 4; q++) acc[i][q] = 0.f;
}

__device__ __forceinline__ void stage128(char* dst, const float* __restrict__ src,
                                         int srcPitch, int t)
{
#pragma unroll
    for (int i = 0; i < 16; i++) {
        int idx = t + i * 128;
        int r = idx >> 4, c4 = idx & 15;
        float4 v = *(const float4*)&src[r * srcPitch + c4 * 4];
        *(uint2*)(dst + r * PITCH + c4 * 8) = make_uint2(bf2(v.x, v.y), bf2(v.z, v.w));
    }
}
__device__ __forceinline__ void stage64(char* dst, const float* __restrict__ src,
                                        int srcPitch, int t)
{
#pragma unroll
    for (int i = 0; i < 8; i++) {
        int idx = t + i * 128;
        int o = idx >> 4, c4 = idx & 15;
        float4 v = *(const float4*)&src[o * srcPitch + c4 * 4];
        *(uint2*)(dst + o * PITCH + c4 * 8) = make_uint2(bf2(v.x, v.y), bf2(v.z, v.w));
    }
}

// ---------------------------------------------------------------------------
// Single fused kernel. grid (32 batch tiles, 64 blocks j), 128 threads.
// ---------------------------------------------------------------------------
__global__ void __launch_bounds__(128, 2) ltc_main(
    const float* __restrict__ y,
    const float* __restrict__ u,
    const float* __restrict__ tau_raw,
    const float* __restrict__ Wi,  const float* __restrict__ bi,
    const float* __restrict__ Wf,  const float* __restrict__ bfw,
    const float* __restrict__ Wr,  const float* __restrict__ brw,
    const float* __restrict__ El,  const float* __restrict__ Elr,
    float* __restrict__ out)
{
    extern __shared__ char sm[];
    const int t     = threadIdx.x;
    const int lane  = t & 31;
    const int warpM = (t >> 5) * 32;
    const int bt    = blockIdx.x;
    const int j     = blockIdx.y;
    const int row0  = bt * 128;

    float* s_br = (float*)(sm + BR_OFF);
    float* s_bf = (float*)(sm + BF_OFF);
    float* s_it = (float*)(sm + IT_OFF);
    const uint32_t smb = smem_u32(sm);

    // ---------------- Stage: bf16 tiles + weights ----------
    stage128(sm + A1_OFF, y + (size_t)row0 * NTOT + j * 64, NTOT, t);
    if (j > 0) {
        stage128(sm + A0_OFF, y + (size_t)row0 * NTOT + (j - 1) * 64, NTOT, t);
        stage64(sm + W0_OFF, Wf + (j - 1) * 4096, 64, t);
    }
    stage64(sm + W1_OFF, Wr  + j * 4096, 64, t);
    stage64(sm + W2_OFF, El  + j * 4096, 64, t);
    stage64(sm + W3_OFF, Elr + j * 4096, 64, t);
    if (t < 64) {
        s_br[t] = brw[j * 64 + t];
        s_bf[t] = (j > 0) ? bfw[(j - 1) * 64 + t] : bi[t];
        float x  = tau_raw[j * 64 + t];
        float sp = (x > 20.f) ? x : log1pf(expf(x));
        s_it[t]  = 1.0f / (sp + TAU_EPS);
    }
    __syncthreads();

    float acc[16][4];
    uint32_t nr_lo[2][8], nr_hi[2][8];   // net_rec packed bf16x2 fragments
    uint32_t no_lo[2][8], no_hi[2][8];   // net_out packed bf16x2 fragments

    // ---------------- Phase 1a: net_rec = tanh(y_cur @ Wr^T + br) ----------
    zero_acc(acc);
    gemm32x64(smb + A1_OFF, smb + W1_OFF, acc, lane, warpM);
    pack_tanh(acc, s_br, nr_lo, nr_hi, lane);

    // ---------------- Phase 1b: net_out ------------------------------------
    zero_acc(acc);
    if (j > 0) {
        gemm32x64(smb + A0_OFF, smb + W0_OFF, acc, lane, warpM);
    } else {
        // net0 = u_t @ W_in^T over K=256 in 4 staged chunks (block-uniform)
        for (int kc = 0; kc < 4; kc++) {
            __syncthreads();
            stage128(sm + A0_OFF, u + (size_t)row0 * IN_DIM + kc * 64, IN_DIM, t);
            stage64(sm + W0_OFF, Wi + kc * 64, IN_DIM, t);
            __syncthreads();
            gemm32x64(smb + A0_OFF, smb + W0_OFF, acc, lane, warpM);
        }
    }
    pack_tanh(acc, s_bf, no_lo, no_hi, lane);

    // ---------------- Phase 2: drive = net_out@El^T + net_rec@Elr^T --------
    zero_acc(acc);
    gemm32x64_reg(smb + W2_OFF, no_lo, no_hi, acc, lane);
    gemm32x64_reg(smb + W3_OFF, nr_lo, nr_hi, acc, lane);

    // ---------------- Epilogue: combine + direct fragment I/O --------------
    // Exact fp32 y reloaded fragment-wise from global (L2-hot from staging).
    {
        const int gm = warpM + (lane >> 2);
        const int nb = (lane & 3) * 2;
#pragma unroll
        for (int mt = 0; mt < 2; mt++)
#pragma unroll
            for (int nt = 0; nt < 8; nt++) {
                int n = nt * 8 + nb;
                float it0 = s_it[n], it1 = s_it[n + 1];
                float2 no0 = ubf2(no_lo[mt][nt]), no1 = ubf2(no_hi[mt][nt]);
                float2 nr0 = ubf2(nr_lo[mt][nt]), nr1 = ubf2(nr_hi[mt][nt]);
                const float* c = acc[mt * 8 + nt];
                int m0 = gm + mt * 16;
                size_t g0 = (size_t)(row0 + m0) * NTOT + j * 64 + n;
                size_t g1 = (size_t)(row0 + m0 + 8) * NTOT + j * 64 + n;
                float2 ya = *(const float2*)&y[g0];
                float2 yc = *(const float2*)&y[g1];
                float2 o0, o1;
                o0.x = __fdividef(ya.x + DT_C * c[0],
                                  1.f + DT_C * (it0 + fabsf(no0.x) + fabsf(nr0.x)));
                o0.y = __fdividef(ya.y + DT_C * c[1],
                                  1.f + DT_C * (it1 + fabsf(no0.y) + fabsf(nr0.y)));
                o1.x = __fdividef(yc.x + DT_C * c[2],
                                  1.f + DT_C * (it0 + fabsf(no1.x) + fabsf(nr1.x)));
                o1.y = __fdividef(yc.y + DT_C * c[3],
                                  1.f + DT_C * (it1 + fabsf(no1.y) + fabsf(nr1.y)));
                *(float2*)&out[g0] = o0;
                *(float2*)&out[g1] = o1;
            }
    }
}

// ---------------------------------------------------------------------------
extern "C" void kernel_launch(void* const* d_in, const int* in_sizes, int n_in,
                              void* d_out, int out_size) {
    const float* y   = (const float*)d_in[0];
    const float* u_t = (const float*)d_in[1];
    const float* tau = (const float*)d_in[2];
    const float* Wi  = (const float*)d_in[3];
    const float* bi  = (const float*)d_in[4];
    const float* Wf  = (const float*)d_in[5];
    const float* bfw = (const float*)d_in[6];
    const float* Wr  = (const float*)d_in[7];
    const float* brw = (const float*)d_in[8];
    const float* El  = (const float*)d_in[9];
    const float* Elr = (const float*)d_in[10];
    float* out = (float*)d_out;

    cudaFuncSetAttribute(ltc_main, cudaFuncAttributeMaxDynamicSharedMemorySize,
                         SMEM_TOTAL);

    ltc_main<<<dim3(BATCH / 128, NB), 128, SMEM_TOTAL>>>(
        y, u_t, tau, Wi, bi, Wf, bfw, Wr, brw, El, Elr, out);
}

// round 13
// speedup vs baseline: 2.2007x; 1.0450x over previous
#include <cuda_runtime.h>
#include <cuda_bf16.h>
#include <cstdint>

#define BATCH   4096
#define NB      64
#define IN_DIM  256
#define NTOT    4096
#define DT_C    0.05f
#define TAU_EPS 1e-6f

// bf16 tile row pitch: 72 elems = 144 bytes (odd 16B-groups -> conflict-free ldmatrix)
#define PITCH   144

// ---------------- SMEM layout (byte offsets) ----------------
#define A0_OFF  0                       // 128 x 64 bf16 (y_prev | u chunk)
#define A1_OFF  18432                   // 128 x 64 bf16 (y_cur)
#define W0_OFF  36864                   // W_fwd[j-1] | W_in chunk
#define W1_OFF  46080                   // W_rec[j]
#define W2_OFF  55296                   // E_l[j]
#define W3_OFF  64512                   // E_l_r[j]
#define BR_OFF  73728
#define BF_OFF  (BR_OFF + 256)
#define IT_OFF  (BF_OFF + 256)
#define SMEM_TOTAL (IT_OFF + 256)       // 74496 B; occupancy pinned to 2 CTAs/SM

// ---------------------------------------------------------------------------
// helpers
// ---------------------------------------------------------------------------
__device__ __forceinline__ uint32_t smem_u32(const void* p) {
    uint32_t a;
    asm("{ .reg .u64 t; cvta.to.shared.u64 t, %1; cvt.u32.u64 %0, t; }"
        : "=r"(a) : "l"(p));
    return a;
}
__device__ __forceinline__ float tanh_fast(float x) {
    float r; asm("tanh.approx.f32 %0, %1;" : "=f"(r) : "f"(x)); return r;
}
__device__ __forceinline__ uint32_t bf2(float lo, float hi) {
    uint32_t r;
    asm("cvt.rn.bf16x2.f32 %0, %1, %2;" : "=r"(r) : "f"(hi), "f"(lo));
    return r;
}
__device__ __forceinline__ float2 ubf2(uint32_t v) {
    __nv_bfloat162 b = *reinterpret_cast<__nv_bfloat162*>(&v);
    return __bfloat1622float2(b);
}
__device__ __forceinline__ void stcs2(float* p, float2 v) {
    asm volatile("st.global.cs.v2.f32 [%0], {%1, %2};"
                 :: "l"(p), "f"(v.x), "f"(v.y) : "memory");
}

#define LDM4(r, addr) \
    asm volatile("ldmatrix.sync.aligned.m8n8.x4.shared.b16 {%0,%1,%2,%3}, [%4];" \
        : "=r"((r)[0]), "=r"((r)[1]), "=r"((r)[2]), "=r"((r)[3]) : "r"(addr))

__device__ __forceinline__ void mma16816(float* c, const uint32_t* a,
                                         uint32_t b0, uint32_t b1) {
    asm volatile(
        "mma.sync.aligned.m16n8k16.row.col.f32.bf16.bf16.f32 "
        "{%0,%1,%2,%3}, {%4,%5,%6,%7}, {%8,%9}, {%0,%1,%2,%3};"
        : "+f"(c[0]), "+f"(c[1]), "+f"(c[2]), "+f"(c[3])
        : "r"(a[0]), "r"(a[1]), "r"(a[2]), "r"(a[3]), "r"(b0), "r"(b1));
}

// Warp computes C[32 x 64] += A_smem[32 x 64] * W_smem[64 x 64]^T
__device__ __forceinline__ void gemm32x64(uint32_t abase, uint32_t wbase,
                                          float acc[16][4], int lane, int warpM)
{
    uint32_t pa = abase + (uint32_t)((warpM + (lane & 7) + ((lane >> 3) & 1) * 8) * PITCH
                                     + ((lane >> 4) * 8) * 2);
    uint32_t pb = wbase + (uint32_t)((((lane & 7) + ((lane >> 4) & 1) * 8)) * PITCH
                                     + (((lane >> 3) & 1) * 8) * 2);
#pragma unroll
    for (int ks = 0; ks < 4; ks++) {
        uint32_t a0[4], a1[4];
        LDM4(a0, pa + ks * 32);
        LDM4(a1, pa + 16 * PITCH + ks * 32);
#pragma unroll
        for (int np = 0; np < 4; np++) {
            uint32_t b[4];
            LDM4(b, pb + np * 16 * PITCH + ks * 32);
            mma16816(acc[np * 2 + 0],     a0, b[0], b[1]);
            mma16816(acc[np * 2 + 1],     a0, b[2], b[3]);
            mma16816(acc[8 + np * 2 + 0], a1, b[0], b[1]);
            mma16816(acc[8 + np * 2 + 1], a1, b[2], b[3]);
        }
    }
}

// Fused phase-2: C[32 x 64] += NO_regs * W2^T + NR_regs * W3^T
// Both B-tile loads issued together for doubled LDSM MLP.
__device__ __forceinline__ void gemm32x64_reg2(uint32_t w2base, uint32_t w3base,
                                               const uint32_t no_lo[2][8],
                                               const uint32_t no_hi[2][8],
                                               const uint32_t nr_lo[2][8],
                                               const uint32_t nr_hi[2][8],
                                               float acc[16][4], int lane)
{
    uint32_t boff = (uint32_t)((((lane & 7) + ((lane >> 4) & 1) * 8)) * PITCH
                               + (((lane >> 3) & 1) * 8) * 2);
    uint32_t pb2 = w2base + boff;
    uint32_t pb3 = w3base + boff;
#pragma unroll
    for (int ks = 0; ks < 4; ks++) {
#pragma unroll
        for (int np = 0; np < 4; np++) {
            uint32_t b2[4], b3[4];
            LDM4(b2, pb2 + np * 16 * PITCH + ks * 32);
            LDM4(b3, pb3 + np * 16 * PITCH + ks * 32);
#pragma unroll
            for (int mt = 0; mt < 2; mt++) {
                uint32_t an[4] = { no_lo[mt][2 * ks], no_hi[mt][2 * ks],
                                   no_lo[mt][2 * ks + 1], no_hi[mt][2 * ks + 1] };
                uint32_t ar[4] = { nr_lo[mt][2 * ks], nr_hi[mt][2 * ks],
                                   nr_lo[mt][2 * ks + 1], nr_hi[mt][2 * ks + 1] };
                mma16816(acc[mt * 8 + np * 2 + 0], an, b2[0], b2[1]);
                mma16816(acc[mt * 8 + np * 2 + 1], an, b2[2], b2[3]);
                mma16816(acc[mt * 8 + np * 2 + 0], ar, b3[0], b3[1]);
                mma16816(acc[mt * 8 + np * 2 + 1], ar, b3[2], b3[3]);
            }
        }
    }
}

// tanh(acc + bias) -> packed bf16x2 fragments in registers
__device__ __forceinline__ void pack_tanh(const float acc[16][4], const float* bias,
                                          uint32_t lo[2][8], uint32_t hi[2][8],
                                          int lane)
{
    const int nb = (lane & 3) * 2;
#pragma unroll
    for (int mt = 0; mt < 2; mt++)
#pragma unroll
        for (int nt = 0; nt < 8; nt++) {
            const float* c = acc[mt * 8 + nt];
            float b0 = bias[nt * 8 + nb], b1 = bias[nt * 8 + nb + 1];
            lo[mt][nt] = bf2(tanh_fast(c[0] + b0), tanh_fast(c[1] + b1));
            hi[mt][nt] = bf2(tanh_fast(c[2] + b0), tanh_fast(c[3] + b1));
        }
}

__device__ __forceinline__ void zero_acc(float acc[16][4]) {
#pragma unroll
    for (int i = 0; i < 16; i++)
#pragma unroll
        for (int q = 0; q < 4; q++) acc[i][q] = 0.f;
}

__device__ __forceinline__ void stage128(char* dst, const float* __restrict__ src,
                                         int srcPitch, int t)
{
#pragma unroll
    for (int i = 0; i < 16; i++) {
        int idx = t + i * 128;
        int r = idx >> 4, c4 = idx & 15;
        float4 v = *(const float4*)&src[r * srcPitch + c4 * 4];
        *(uint2*)(dst + r * PITCH + c4 * 8) = make_uint2(bf2(v.x, v.y), bf2(v.z, v.w));
    }
}
__device__ __forceinline__ void stage64(char* dst, const float* __restrict__ src,
                                        int srcPitch, int t)
{
#pragma unroll
    for (int i = 0; i < 8; i++) {
        int idx = t + i * 128;
        int o = idx >> 4, c4 = idx & 15;
        float4 v = *(const float4*)&src[o * srcPitch + c4 * 4];
        *(uint2*)(dst + o * PITCH + c4 * 8) = make_uint2(bf2(v.x, v.y), bf2(v.z, v.w));
    }
}

// ---------------------------------------------------------------------------
// Single fused kernel. grid (32 batch tiles, 64 blocks j), 128 threads.
// ---------------------------------------------------------------------------
__global__ void __launch_bounds__(128, 2) ltc_main(
    const float* __restrict__ y,
    const float* __restrict__ u,
    const float* __restrict__ tau_raw,
    const float* __restrict__ Wi,  const float* __restrict__ bi,
    const float* __restrict__ Wf,  const float* __restrict__ bfw,
    const float* __restrict__ Wr,  const float* __restrict__ brw,
    const float* __restrict__ El,  const float* __restrict__ Elr,
    float* __restrict__ out)
{
    extern __shared__ char sm[];
    const int t     = threadIdx.x;
    const int lane  = t & 31;
    const int warpM = (t >> 5) * 32;
    const int bt    = blockIdx.x;
    const int j     = blockIdx.y;
    const int row0  = bt * 128;

    float* s_br = (float*)(sm + BR_OFF);
    float* s_bf = (float*)(sm + BF_OFF);
    float* s_it = (float*)(sm + IT_OFF);
    const uint32_t smb = smem_u32(sm);

    // ---------------- Stage: bf16 tiles + weights ----------
    stage128(sm + A1_OFF, y + (size_t)row0 * NTOT + j * 64, NTOT, t);
    if (j > 0) {
        stage128(sm + A0_OFF, y + (size_t)row0 * NTOT + (j - 1) * 64, NTOT, t);
        stage64(sm + W0_OFF, Wf + (j - 1) * 4096, 64, t);
    }
    stage64(sm + W1_OFF, Wr  + j * 4096, 64, t);
    stage64(sm + W2_OFF, El  + j * 4096, 64, t);
    stage64(sm + W3_OFF, Elr + j * 4096, 64, t);
    if (t < 64) {
        s_br[t] = brw[j * 64 + t];
        s_bf[t] = (j > 0) ? bfw[(j - 1) * 64 + t] : bi[t];
        float x  = tau_raw[j * 64 + t];
        float sp = (x > 20.f) ? x : log1pf(expf(x));
        s_it[t]  = 1.0f / (sp + TAU_EPS);
    }
    __syncthreads();

    float acc[16][4];
    uint32_t nr_lo[2][8], nr_hi[2][8];   // net_rec packed bf16x2 fragments
    uint32_t no_lo[2][8], no_hi[2][8];   // net_out packed bf16x2 fragments

    // ---------------- Phase 1a: net_rec = tanh(y_cur @ Wr^T + br) ----------
    zero_acc(acc);
    gemm32x64(smb + A1_OFF, smb + W1_OFF, acc, lane, warpM);
    pack_tanh(acc, s_br, nr_lo, nr_hi, lane);

    // ---------------- Phase 1b: net_out ------------------------------------
    zero_acc(acc);
    if (j > 0) {
        gemm32x64(smb + A0_OFF, smb + W0_OFF, acc, lane, warpM);
    } else {
        // net0 = u_t @ W_in^T over K=256 in 4 staged chunks (block-uniform)
        for (int kc = 0; kc < 4; kc++) {
            __syncthreads();
            stage128(sm + A0_OFF, u + (size_t)row0 * IN_DIM + kc * 64, IN_DIM, t);
            stage64(sm + W0_OFF, Wi + kc * 64, IN_DIM, t);
            __syncthreads();
            gemm32x64(smb + A0_OFF, smb + W0_OFF, acc, lane, warpM);
        }
    }
    pack_tanh(acc, s_bf, no_lo, no_hi, lane);

    // ---------------- Phase 2: drive = net_out@El^T + net_rec@Elr^T --------
    zero_acc(acc);
    gemm32x64_reg2(smb + W2_OFF, smb + W3_OFF,
                   no_lo, no_hi, nr_lo, nr_hi, acc, lane);

    // ---------------- Epilogue: combine + direct fragment I/O --------------
    // Exact fp32 y reloaded fragment-wise from global (L2-hot from staging).
    {
        const int gm = warpM + (lane >> 2);
        const int nb = (lane & 3) * 2;
#pragma unroll
        for (int mt = 0; mt < 2; mt++)
#pragma unroll
            for (int nt = 0; nt < 8; nt++) {
                int n = nt * 8 + nb;
                float it0 = s_it[n], it1 = s_it[n + 1];
                float2 no0 = ubf2(no_lo[mt][nt]), no1 = ubf2(no_hi[mt][nt]);
                float2 nr0 = ubf2(nr_lo[mt][nt]), nr1 = ubf2(nr_hi[mt][nt]);
                const float* c = acc[mt * 8 + nt];
                int m0 = gm + mt * 16;
                size_t g0 = (size_t)(row0 + m0) * NTOT + j * 64 + n;
                size_t g1 = (size_t)(row0 + m0 + 8) * NTOT + j * 64 + n;
                float2 ya = __ldg((const float2*)&y[g0]);
                float2 yc = __ldg((const float2*)&y[g1]);
                float2 o0, o1;
                o0.x = __fdividef(ya.x + DT_C * c[0],
                                  1.f + DT_C * (it0 + fabsf(no0.x) + fabsf(nr0.x)));
                o0.y = __fdividef(ya.y + DT_C * c[1],
                                  1.f + DT_C * (it1 + fabsf(no0.y) + fabsf(nr0.y)));
                o1.x = __fdividef(yc.x + DT_C * c[2],
                                  1.f + DT_C * (it0 + fabsf(no1.x) + fabsf(nr1.x)));
                o1.y = __fdividef(yc.y + DT_C * c[3],
                                  1.f + DT_C * (it1 + fabsf(no1.y) + fabsf(nr1.y)));
                stcs2(&out[g0], o0);
                stcs2(&out[g1], o1);
            }
    }
}

// ---------------------------------------------------------------------------
extern "C" void kernel_launch(void* const* d_in, const int* in_sizes, int n_in,
                              void* d_out, int out_size) {
    const float* y   = (const float*)d_in[0];
    const float* u_t = (const float*)d_in[1];
    const float* tau = (const float*)d_in[2];
    const float* Wi  = (const float*)d_in[3];
    const float* bi  = (const float*)d_in[4];
    const float* Wf  = (const float*)d_in[5];
    const float* bfw = (const float*)d_in[6];
    const float* Wr  = (const float*)d_in[7];
    const float* brw = (const float*)d_in[8];
    const float* El  = (const float*)d_in[9];
    const float* Elr = (const float*)d_in[10];
    float* out = (float*)d_out;

    cudaFuncSetAttribute(ltc_main, cudaFuncAttributeMaxDynamicSharedMemorySize,
                         SMEM_TOTAL);

    ltc_main<<<dim3(BATCH / 128, NB), 128, SMEM_TOTAL>>>(
        y, u_t, tau, Wi, bi, Wf, bfw, Wr, brw, El, Elr, out);
}